// round 4
// baseline (speedup 1.0000x reference)
#include <cuda_runtime.h>
#include <cstdint>

// x: (B=8, C=16, T=2000, F=128) fp32. Per (b,c,f) column: POOL=10 block sums,
// causal cumulative mean/var over blocks, normalize. Single pass.
//
// One CTA per (b*C+c) column. A pooled block is 10*128 floats = 5120 CONTIGUOUS
// bytes, so each block is fetched with ONE cp.async.bulk (TMA engine — not
// bound by the per-warp ~55-outstanding-LDG cap that limited the cp.async
// version to 4.3TB/s). Ring of DD=25 blocks in dynamic smem, full/empty
// mbarriers. 256 threads: half = 5 rows of the block, f = 0..127; halves
// exchange partial sums via double-buffered smem + one bar per block.

#define TT      2000
#define FF      128
#define PP      10
#define TT1     200
#define DD      25                 // ring depth in blocks (divides TT1)
#define BLK_B   5120               // bytes per pooled block
#define BLK_F   1280               // floats per pooled block
#define EPSV    1e-5f

#define RING_BYTES   (DD * BLK_B)              // 128000
#define PART_OFF     RING_BYTES                // float2 part[2][2][128] = 4096 B
#define MBAR_OFF     (RING_BYTES + 4096)       // DD * 16 B
#define SMEM_TOTAL   (MBAR_OFF + DD * 16)

__device__ __forceinline__ uint32_t s2u32(const void* p) {
    uint32_t a;
    asm("{ .reg .u64 t; cvta.to.shared.u64 t, %1; cvt.u32.u64 %0, t; }"
        : "=r"(a) : "l"(p));
    return a;
}
__device__ __forceinline__ void mbar_init(uint32_t m, uint32_t cnt) {
    asm volatile("mbarrier.init.shared.b64 [%0], %1;" :: "r"(m), "r"(cnt) : "memory");
}
__device__ __forceinline__ void mbar_expect_tx(uint32_t m, uint32_t bytes) {
    asm volatile("mbarrier.arrive.expect_tx.shared.b64 _, [%0], %1;"
                 :: "r"(m), "r"(bytes) : "memory");
}
__device__ __forceinline__ void mbar_arrive(uint32_t m) {
    asm volatile("mbarrier.arrive.shared.b64 _, [%0];" :: "r"(m) : "memory");
}
__device__ __forceinline__ void mbar_wait(uint32_t m, uint32_t ph) {
    uint32_t done;
    asm volatile(
        "{\n\t.reg .pred p;\n\t"
        "mbarrier.try_wait.parity.acquire.cta.shared::cta.b64 p, [%1], %2;\n\t"
        "selp.b32 %0, 1, 0, p;\n\t}"
        : "=r"(done) : "r"(m), "r"(ph) : "memory");
    if (!done) {
        asm volatile(
            "{\n\t.reg .pred P1;\n\t"
            "W_%=:\n\t"
            "mbarrier.try_wait.parity.acquire.cta.shared::cta.b64 P1, [%0], %1, 0x989680;\n\t"
            "@P1 bra.uni D_%=;\n\t"
            "bra.uni W_%=;\n\t"
            "D_%=:\n\t}"
            :: "r"(m), "r"(ph) : "memory");
    }
}
__device__ __forceinline__ void bulk_g2s(uint32_t sdst, const void* gsrc,
                                         uint32_t bytes, uint32_t mbar) {
    asm volatile(
        "cp.async.bulk.shared::cta.global.mbarrier::complete_tx::bytes [%0], [%1], %2, [%3];"
        :: "r"(sdst), "l"(gsrc), "r"(bytes), "r"(mbar) : "memory");
}

__global__ void __launch_bounds__(256, 1)
inorm_kernel(const float* __restrict__ x, float* __restrict__ out)
{
    extern __shared__ float smem[];
    const uint32_t sbase = s2u32(smem);

    const int col  = blockIdx.x;            // 0..127
    const int tid  = threadIdx.x;
    const int half = tid >> 7;              // 0: rows 0-4, 1: rows 5-9
    const int f    = tid & 127;

    const float* gcol = x   + (size_t)col * (TT * FF);
    float*       ocol = out + (size_t)col * (TT * FF) + f;

    float2* part = (float2*)((char*)smem + PART_OFF);   // [buf][half][f]
    const uint32_t mb = sbase + MBAR_OFF;
    #define FULL(s)  (mb + (s) * 16)
    #define EMPTY(s) (mb + (s) * 16 + 8)

    if (tid == 0) {
        #pragma unroll
        for (int s = 0; s < DD; s++) {
            mbar_init(FULL(s), 1);
            mbar_init(EMPTY(s), 256);
        }
    }
    __syncthreads();
    asm volatile("fence.proxy.async.shared::cta;" ::: "memory");

    // Prologue: fill ring with blocks 0..DD-1
    if (tid == 0) {
        #pragma unroll 1
        for (int s = 0; s < DD; s++) {
            mbar_expect_tx(FULL(s), BLK_B);
            bulk_g2s(sbase + s * BLK_B, gcol + s * BLK_F, BLK_B, FULL(s));
        }
    }

    float sAcc = 0.f, s2Acc = 0.f;
    int s = 0, ph = 0;

    #pragma unroll 1
    for (int k = 0; k < TT1; k++) {
        mbar_wait(FULL(s), ph);

        // Consume this half's 5 rows of block k
        const float* rp = smem + s * BLK_F + (half * 5) * FF + f;
        float a[5];
        #pragma unroll
        for (int i = 0; i < 5; i++) a[i] = rp[i * FF];

        float bs = 0.f, bs2 = 0.f;
        #pragma unroll
        for (int i = 0; i < 5; i++) { bs += a[i]; bs2 = fmaf(a[i], a[i], bs2); }

        const int buf = k & 1;
        part[(buf * 2 + half) * FF + f] = make_float2(bs, bs2);
        __syncthreads();
        const float2 p0 = part[(buf * 2 + 0) * FF + f];
        const float2 p1 = part[(buf * 2 + 1) * FF + f];
        sAcc  += p0.x + p1.x;
        s2Acc += p0.y + p1.y;

        const float invn = __fdividef(1.0f, (float)((k + 1) * PP));
        const float m    = sAcc  * invn;
        const float m2   = s2Acc * invn;
        const float v    = fmaf(-m, m, m2);
        const float rr   = rsqrtf(v + EPSV);

        float* og = ocol + (k * PP + half * 5) * FF;
        #pragma unroll
        for (int i = 0; i < 5; i++) og[i * FF] = (a[i] - m) * rr;

        mbar_arrive(EMPTY(s));

        if (tid == 0) {
            const int kn = k + DD;
            if (kn < TT1) {
                mbar_wait(EMPTY(s), ph);
                mbar_expect_tx(FULL(s), BLK_B);
                bulk_g2s(sbase + s * BLK_B, gcol + kn * BLK_F, BLK_B, FULL(s));
            }
        }

        if (++s == DD) { s = 0; ph ^= 1; }
    }
}

extern "C" void kernel_launch(void* const* d_in, const int* in_sizes, int n_in,
                              void* d_out, int out_size)
{
    const float* x   = (const float*)d_in[0];
    float*       out = (float*)d_out;
    cudaFuncSetAttribute(inorm_kernel,
                         cudaFuncAttributeMaxDynamicSharedMemorySize, SMEM_TOTAL);
    inorm_kernel<<<128, 256, SMEM_TOTAL>>>(x, out);
}

// round 5
// speedup vs baseline: 1.2187x; 1.2187x over previous
#include <cuda_runtime.h>
#include <cstdint>

// x: (B=8, C=16, T=2000, F=128) fp32. Per (b,c,f) column: POOL=10 block sums,
// causal cumulative mean/var over pooled blocks, normalize. Single pass.
//
// One CTA per (b*C+c) column, 512 threads. Ring of NS=4 tiles x TB=8 pooled
// blocks (40960 B) filled by cp.async.bulk (TMA). Per tile: parallel block
// sums -> tiny 8-step serial cumsum on 128 f-threads -> parallel float4
// normalize + coalesced STG.128. The serial scan is reduced to ~8 cheap steps
// per tile instead of per-block global serialization.

#define TT      2000
#define FF      128
#define PP      10
#define TT1     200
#define TB      8                   // pooled blocks per tile
#define NT      25                  // tiles = TT1/TB
#define NS      4                   // ring stages
#define TILE_F  (TB * PP * FF)      // 10240 floats
#define TILE_B  (TILE_F * 4)        // 40960 bytes
#define EPSV    1e-5f

#define BS_OFF    (NS * TILE_B)                 // float2 bs[TB][FF]   = 8192 B
#define M_OFF     (BS_OFF + TB * FF * 8)        // float  m[TB][FF]    = 4096 B
#define R_OFF     (M_OFF + TB * FF * 4)         // float  r[TB][FF]    = 4096 B
#define MBAR_OFF  (R_OFF + TB * FF * 4)
#define SMEM_TOTAL (MBAR_OFF + NS * 8)

__device__ __forceinline__ uint32_t s2u32(const void* p) {
    uint32_t a;
    asm("{ .reg .u64 t; cvta.to.shared.u64 t, %1; cvt.u32.u64 %0, t; }"
        : "=r"(a) : "l"(p));
    return a;
}
__device__ __forceinline__ void mbar_init(uint32_t m, uint32_t cnt) {
    asm volatile("mbarrier.init.shared.b64 [%0], %1;" :: "r"(m), "r"(cnt) : "memory");
}
__device__ __forceinline__ void mbar_expect_tx(uint32_t m, uint32_t bytes) {
    asm volatile("mbarrier.arrive.expect_tx.shared.b64 _, [%0], %1;"
                 :: "r"(m), "r"(bytes) : "memory");
}
__device__ __forceinline__ void mbar_wait(uint32_t m, uint32_t ph) {
    uint32_t done;
    asm volatile(
        "{\n\t.reg .pred p;\n\t"
        "mbarrier.try_wait.parity.acquire.cta.shared::cta.b64 p, [%1], %2;\n\t"
        "selp.b32 %0, 1, 0, p;\n\t}"
        : "=r"(done) : "r"(m), "r"(ph) : "memory");
    if (!done) {
        asm volatile(
            "{\n\t.reg .pred P1;\n\t"
            "W_%=:\n\t"
            "mbarrier.try_wait.parity.acquire.cta.shared::cta.b64 P1, [%0], %1, 0x989680;\n\t"
            "@P1 bra.uni D_%=;\n\t"
            "bra.uni W_%=;\n\t"
            "D_%=:\n\t}"
            :: "r"(m), "r"(ph) : "memory");
    }
}
__device__ __forceinline__ void bulk_g2s(uint32_t sdst, const void* gsrc,
                                         uint32_t bytes, uint32_t mbar) {
    asm volatile(
        "cp.async.bulk.shared::cta.global.mbarrier::complete_tx::bytes [%0], [%1], %2, [%3];"
        :: "r"(sdst), "l"(gsrc), "r"(bytes), "r"(mbar) : "memory");
}

__global__ void __launch_bounds__(512, 1)
inorm_kernel(const float* __restrict__ x, float* __restrict__ out)
{
    extern __shared__ float smem[];
    const uint32_t sbase = s2u32(smem);

    const int col = blockIdx.x;        // 0..127
    const int tid = threadIdx.x;
    const int f   = tid & 127;
    const int g   = tid >> 7;          // 0..3

    const float* gcol  = x + (size_t)col * (TT * FF);
    float4*      ocol4 = (float4*)(out + (size_t)col * (TT * FF));

    float2* bsArr = (float2*)((char*)smem + BS_OFF);
    float*  mArr  = (float*)((char*)smem + M_OFF);
    float*  rArr  = (float*)((char*)smem + R_OFF);
    const uint32_t mb = sbase + MBAR_OFF;
    #define FULLB(s) (mb + (s) * 8)

    if (tid == 0) {
        #pragma unroll
        for (int s = 0; s < NS; s++) mbar_init(FULLB(s), 1);
    }
    __syncthreads();
    asm volatile("fence.proxy.async.shared::cta;" ::: "memory");

    // Prologue: fill ring with tiles 0..NS-1
    if (tid == 0) {
        #pragma unroll
        for (int s = 0; s < NS; s++) {
            mbar_expect_tx(FULLB(s), TILE_B);
            bulk_g2s(sbase + s * TILE_B, gcol + s * TILE_F, TILE_B, FULLB(s));
        }
    }

    float sAcc = 0.f, s2Acc = 0.f;   // live only in tid < 128
    int st = 0, ph = 0;

    #pragma unroll 1
    for (int t = 0; t < NT; t++) {
        mbar_wait(FULLB(st), ph);

        const float* tile = smem + st * TILE_F;

        // ── step A: parallel block sums. thread (g,f) handles blocks 2g, 2g+1
        #pragma unroll
        for (int bb = 0; bb < 2; bb++) {
            const int b = 2 * g + bb;
            const float* rp = tile + b * (PP * FF) + f;
            float bs = 0.f, bs2 = 0.f;
            #pragma unroll
            for (int i = 0; i < PP; i++) {
                const float a = rp[i * FF];
                bs += a; bs2 = fmaf(a, a, bs2);
            }
            bsArr[b * FF + f] = make_float2(bs, bs2);
        }
        __syncthreads();

        // ── step B: tiny serial cumsum over TB blocks (128 f-threads)
        if (tid < FF) {
            #pragma unroll
            for (int b = 0; b < TB; b++) {
                const float2 bs = bsArr[b * FF + f];
                sAcc += bs.x; s2Acc += bs.y;
                const float invn = __fdividef(1.0f, (float)((t * TB + b + 1) * PP));
                const float m    = sAcc * invn;
                const float v    = fmaf(-m, m, s2Acc * invn);
                mArr[b * FF + f] = m;
                rArr[b * FF + f] = rsqrtf(v + EPSV);
            }
        }
        __syncthreads();

        // ── step C: parallel normalize, 5 float4 per thread, coalesced STG.128
        const float4* tile4 = (const float4*)tile;
        const float4* m4a   = (const float4*)mArr;
        const float4* r4a   = (const float4*)rArr;
        float4* og4 = ocol4 + t * (TILE_F / 4);
        #pragma unroll
        for (int i = 0; i < 5; i++) {
            const int j   = tid + 512 * i;    // 0..2559
            const int row = j >> 5;           // 0..79
            const int b   = row / PP;         // block in tile
            const int c4  = j & 31;           // float4 group in f
            const float4 xv = tile4[j];
            const float4 mv = m4a[b * 32 + c4];
            const float4 rv = r4a[b * 32 + c4];
            float4 rres;
            rres.x = (xv.x - mv.x) * rv.x;
            rres.y = (xv.y - mv.y) * rv.y;
            rres.z = (xv.z - mv.z) * rv.z;
            rres.w = (xv.w - mv.w) * rv.w;
            og4[j] = rres;
        }
        __syncthreads();   // everyone done reading stage st

        // ── refill stage st with tile t+NS
        if (tid == 0) {
            const int tn = t + NS;
            if (tn < NT) {
                mbar_expect_tx(FULLB(st), TILE_B);
                bulk_g2s(sbase + st * TILE_B, gcol + tn * TILE_F, TILE_B, FULLB(st));
            }
        }
        if (++st == NS) { st = 0; ph ^= 1; }
    }
}

extern "C" void kernel_launch(void* const* d_in, const int* in_sizes, int n_in,
                              void* d_out, int out_size)
{
    const float* x   = (const float*)d_in[0];
    float*       out = (float*)d_out;
    cudaFuncSetAttribute(inorm_kernel,
                         cudaFuncAttributeMaxDynamicSharedMemorySize, SMEM_TOTAL);
    inorm_kernel<<<128, 512, SMEM_TOTAL>>>(x, out);
}